// round 12
// baseline (speedup 1.0000x reference)
#include <cuda_runtime.h>
#include <cstdint>

// =========================================================================
// EuclideanGraphDecoder on GB300 (sm_103a via compute_103 baseline PTX)
// B=8, N=2048, latent=64, hidden=128, out=64, NORM=1.
//
// R10: unified tf32 mma.sync GEMM. CTA tile 128x128 with 512 threads
// (16 warps, 4Mx4N, warp tile 32x32) for 4 warps/SMSP latency hiding.
// cp.async 4-stage pipeline, one barrier per chunk, ldmatrix A fragments.
// =========================================================================

#define BATCH   8
#define NNODES  2048
#define HID     128
#define ROWS_T  (BATCH * NNODES)     // 16384
#define NTHREADS 512

__device__ float g_buf0[ROWS_T * HID];     // msg (node-major, tf32-rounded)
__device__ float g_buf1[ROWS_T * HID];     // h   (node-major, fp32)

// ---------------------------------------------------------------- helpers
__device__ __forceinline__ uint32_t cvt_rna_tf32(float x) {
    uint32_t y;
    asm("cvt.rna.tf32.f32 %0, %1;" : "=r"(y) : "f"(x));
    return y;
}
__device__ __forceinline__ uint32_t cvt_rna_tf32_u(uint32_t x) {
    uint32_t y;
    asm("cvt.rna.tf32.f32 %0, %1;" : "=r"(y) : "r"(x));
    return y;
}
__device__ __forceinline__ uint32_t smem_u32(const void* p) {
    uint32_t a;
    asm("{ .reg .u64 t; cvta.to.shared.u64 t, %1; cvt.u32.u64 %0, t; }" : "=r"(a) : "l"(p));
    return a;
}
__device__ __forceinline__ void cp_async16(uint32_t dst, const void* src) {
    asm volatile("cp.async.cg.shared.global [%0], [%1], 16;" :: "r"(dst), "l"(src));
}
#define CP_COMMIT() asm volatile("cp.async.commit_group;" ::: "memory")

__device__ __forceinline__ void ldsm_x4(uint32_t& r0, uint32_t& r1, uint32_t& r2, uint32_t& r3,
                                        uint32_t addr) {
    asm volatile("ldmatrix.sync.aligned.m8n8.x4.shared.b16 {%0,%1,%2,%3}, [%4];"
                 : "=r"(r0), "=r"(r1), "=r"(r2), "=r"(r3) : "r"(addr));
}

__device__ __forceinline__ void mma_tf32(float& c0, float& c1, float& c2, float& c3,
                                         uint32_t a0, uint32_t a1, uint32_t a2, uint32_t a3,
                                         uint32_t b0, uint32_t b1) {
    asm volatile(
        "mma.sync.aligned.m16n8k8.row.col.f32.tf32.tf32.f32 "
        "{%0,%1,%2,%3}, {%4,%5,%6,%7}, {%8,%9}, {%0,%1,%2,%3};"
        : "+f"(c0), "+f"(c1), "+f"(c2), "+f"(c3)
        : "r"(a0), "r"(a1), "r"(a2), "r"(a3), "r"(b0), "r"(b1));
}

// =========================================================================
// Unified tf32 GEMM:  C[b, m0:m0+128, 0:128] = op( A[b,:,0:K] @ B[b,0:K,0:128] )
// CTA 128x128, BK=32 chunks, 4-stage cp.async, 16 warps 4(M)x4(N),
// warp tile 32x32 = 2x4 m16n8k8.
// =========================================================================
#define BK      32
#define STG     4
#define ASTRIDE 36
#define BSTRIDE 136
#define A_FLTS  (128 * ASTRIDE)      // 4608
#define B_FLTS  (BK * BSTRIDE)       // 4352
#define STG_FLTS (A_FLTS + B_FLTS)   // 8960
#define STG_BYTES (STG_FLTS * 4)     // 35840
#define GEMM_SMEM (STG * STG_BYTES)  // 143360 bytes

__device__ __forceinline__ void stage_chunk(uint32_t smb, int s,
                                            const float* Ap, const float* Bp,
                                            int k0, int tid, int lda)
{
    const uint32_t sa = smb + (uint32_t)s * STG_BYTES;
    const uint32_t sb = sa + A_FLTS * 4u;
    // A: 128 rows x 8 float4 = 1024 float4 -> 2 per thread
#pragma unroll
    for (int r = 0; r < 2; r++) {
        const int idx  = tid + NTHREADS * r;
        const int arow = idx >> 3, aseg = idx & 7;
        cp_async16(sa + (uint32_t)(arow * ASTRIDE + aseg * 4) * 4u,
                   Ap + (size_t)arow * lda + k0 + aseg * 4);
    }
    // B: 32 rows x 32 float4 = 1024 float4 -> 2 per thread
#pragma unroll
    for (int r = 0; r < 2; r++) {
        const int idx  = tid + NTHREADS * r;
        const int brow = idx >> 5, bseg = idx & 31;
        cp_async16(sb + (uint32_t)(brow * BSTRIDE + bseg * 4) * 4u,
                   Bp + (size_t)(k0 + brow) * HID + bseg * 4);
    }
    CP_COMMIT();
}

template<bool RELU, bool BIAS, bool ROUND, bool CVTB>
__global__ __launch_bounds__(NTHREADS, 1)
void mma_gemm_kernel(const float* __restrict__ A, const float* __restrict__ B,
                     const float* __restrict__ bias, float* __restrict__ C,
                     int K, int lda, size_t sA, size_t sB, size_t sC)
{
    extern __shared__ float smf[];
    const uint32_t smb = smem_u32(smf);

    const int tid   = threadIdx.x;
    const int lane  = tid & 31;
    const int wid   = tid >> 5;        // 0..15
    const int g     = lane >> 2;       // 0..7
    const int tig   = lane & 3;        // 0..3
    const int mbase = (wid & 3) * 32;  // 4 warps along M
    const int nbase = (wid >> 2) * 32; // 4 warps along N

    // ldmatrix per-thread source row/col inside the 16x8 fragment
    const int mi   = lane >> 3;               // matrix index 0..3
    const int arow = (lane & 7) + (mi & 1) * 8;
    const int acol = (mi >> 1) * 4;
    uint32_t a_off[2];
#pragma unroll
    for (int t = 0; t < 2; t++)
        a_off[t] = (uint32_t)(((mbase + t * 16 + arow) * ASTRIDE + acol) * 4);

    const int batch = blockIdx.y;
    const int m0    = blockIdx.x * 128;

    const float* Ap = A + (size_t)batch * sA + (size_t)m0 * lda;
    const float* Bp = B + (size_t)batch * sB;

    float acc[2][4][4];
#pragma unroll
    for (int t = 0; t < 2; t++)
#pragma unroll
        for (int u = 0; u < 4; u++)
#pragma unroll
            for (int q = 0; q < 4; q++) acc[t][u][q] = 0.0f;

    const int kiters = K / BK;

    int committed = 0;
#pragma unroll
    for (int p = 0; p < STG - 1; p++)
        if (p < kiters) { stage_chunk(smb, p, Ap, Bp, p * BK, tid, lda); committed++; }

    for (int it = 0; it < kiters; it++) {
        const int pend = committed - it - 1;
        if (pend <= 0)      asm volatile("cp.async.wait_group 0;" ::: "memory");
        else if (pend == 1) asm volatile("cp.async.wait_group 1;" ::: "memory");
        else                asm volatile("cp.async.wait_group 2;" ::: "memory");
        __syncthreads();
        // single barrier per chunk: the refill below writes stage (it+3)&3,
        // whose last reads happened at it-1 and are ordered by this barrier.

        if (it + STG - 1 < kiters) {
            stage_chunk(smb, (it + STG - 1) & (STG - 1), Ap, Bp, (it + STG - 1) * BK, tid, lda);
            committed++;
        }

        const uint32_t sa = smb + (uint32_t)(it & (STG - 1)) * STG_BYTES;
        const uint32_t* bsu = (const uint32_t*)(smf + (it & (STG - 1)) * STG_FLTS + A_FLTS);

#pragma unroll
        for (int ks = 0; ks < 4; ks++) {
            const int k = ks * 8;
            uint32_t af[2][4];
#pragma unroll
            for (int t = 0; t < 2; t++) {
                ldsm_x4(af[t][0], af[t][1], af[t][2], af[t][3],
                        sa + a_off[t] + (uint32_t)(k * 4));
#pragma unroll
                for (int q = 0; q < 4; q++) af[t][q] = cvt_rna_tf32_u(af[t][q]);
            }
#pragma unroll
            for (int u = 0; u < 4; u++) {
                const int n = nbase + u * 8 + g;
                uint32_t b0 = bsu[(k + tig) * BSTRIDE + n];
                uint32_t b1 = bsu[(k + tig + 4) * BSTRIDE + n];
                if (CVTB) { b0 = cvt_rna_tf32_u(b0); b1 = cvt_rna_tf32_u(b1); }
#pragma unroll
                for (int t = 0; t < 2; t++)
                    mma_tf32(acc[t][u][0], acc[t][u][1], acc[t][u][2], acc[t][u][3],
                             af[t][0], af[t][1], af[t][2], af[t][3], b0, b1);
            }
        }
    }

    // ---- epilogue ----
    float* Cp = C + (size_t)batch * sC + (size_t)m0 * HID;
#pragma unroll
    for (int t = 0; t < 2; t++) {
        const int r0 = mbase + t * 16 + g;
#pragma unroll
        for (int u = 0; u < 4; u++) {
            const int c = nbase + u * 8 + 2 * tig;
            float v[4] = { acc[t][u][0], acc[t][u][1], acc[t][u][2], acc[t][u][3] };
            if (BIAS) {
                const float bc0 = bias[c], bc1 = bias[c + 1];
                v[0] += bc0; v[1] += bc1; v[2] += bc0; v[3] += bc1;
            }
#pragma unroll
            for (int q = 0; q < 4; q++) {
                if (RELU)  v[q] = fmaxf(v[q], 0.0f);
                if (ROUND) v[q] = __uint_as_float(cvt_rna_tf32(v[q]));
            }
            float2 v0 = { v[0], v[1] };
            float2 v1 = { v[2], v[3] };
            *(float2*)(Cp + (size_t)r0 * HID + c)       = v0;
            *(float2*)(Cp + (size_t)(r0 + 8) * HID + c) = v1;
        }
    }
}

// =========================================================================
// Output projection: out = (h @ Wout + bout) * mask     (fp32 FFMA)
// =========================================================================
__global__ __launch_bounds__(256)
void final_proj_kernel(const float* __restrict__ h, const float* __restrict__ W,
                       const float* __restrict__ bias, const float* __restrict__ mask,
                       float* __restrict__ out)
{
    __shared__ float Ws[128][64];
    __shared__ float xs[16][128];
    __shared__ float bs[64];

    const int tid = threadIdx.x;
    for (int i = tid; i < 2048; i += 256)
        ((float4*)&Ws[0][0])[i] = ((const float4*)W)[i];
    if (tid < 64) bs[tid] = bias[tid];

    const int row0 = blockIdx.x * 16;
    for (int i = tid; i < 512; i += 256)
        ((float4*)&xs[0][0])[i] = *(const float4*)(h + (size_t)row0 * 128 + i * 4);
    __syncthreads();

    const int rl = tid >> 4;
    const int c4 = (tid & 15) * 4;

    float acc[4];
#pragma unroll
    for (int q = 0; q < 4; q++) acc[q] = bs[c4 + q];

#pragma unroll 8
    for (int d = 0; d < 128; d++) {
        const float x = xs[rl][d];
        const float4 w = *(const float4*)&Ws[d][c4];
        acc[0] += x * w.x;
        acc[1] += x * w.y;
        acc[2] += x * w.z;
        acc[3] += x * w.w;
    }

    const float m = mask[row0 + rl];
    float4 v = {acc[0] * m, acc[1] * m, acc[2] * m, acc[3] * m};
    *(float4*)(out + (size_t)(row0 + rl) * 64 + c4) = v;
}

// =========================================================================
// Launcher
// =========================================================================
extern "C" void kernel_launch(void* const* d_in, const int* in_sizes, int n_in,
                              void* d_out, int out_size)
{
    const float* latent = (const float*)d_in[0];
    const float* adj    = (const float*)d_in[1];
    const float* mask   = (const float*)d_in[2];
    const float* W0     = (const float*)d_in[3];
    const float* b0     = (const float*)d_in[4];
    const float* W1     = (const float*)d_in[5];
    const float* b1     = (const float*)d_in[6];
    const float* W2     = (const float*)d_in[7];
    const float* b2     = (const float*)d_in[8];
    const float* Wout   = (const float*)d_in[9];
    const float* bout   = (const float*)d_in[10];
    float*       out    = (float*)d_out;

    float *buf0 = nullptr, *buf1 = nullptr;
    cudaGetSymbolAddress((void**)&buf0, g_buf0);
    cudaGetSymbolAddress((void**)&buf1, g_buf1);

    auto lin = mma_gemm_kernel<false, true, true, true>;    // bias + round, cvt weights
    auto agg = mma_gemm_kernel<true, false, false, false>;  // relu, B pre-rounded
    cudaFuncSetAttribute(lin, cudaFuncAttributeMaxDynamicSharedMemorySize, GEMM_SMEM);
    cudaFuncSetAttribute(agg, cudaFuncAttributeMaxDynamicSharedMemorySize, GEMM_SMEM);

    const dim3 gridLin(ROWS_T / 128, 1);       // 128 CTAs, batch folded into M
    const dim3 gridAgg(NNODES / 128, BATCH);   // 16 x 8 = 128 CTAs
    const size_t sAdj = (size_t)NNODES * NNODES;
    const size_t sH   = (size_t)NNODES * HID;

    // layer 0
    lin<<<gridLin, NTHREADS, GEMM_SMEM>>>(latent, W0, b0, buf0, 64, 64, 0, 0, 0);
    agg<<<gridAgg, NTHREADS, GEMM_SMEM>>>(adj, buf0, nullptr, buf1, NNODES, NNODES, sAdj, sH, sH);

    // layer 1
    lin<<<gridLin, NTHREADS, GEMM_SMEM>>>(buf1, W1, b1, buf0, 128, 128, 0, 0, 0);
    agg<<<gridAgg, NTHREADS, GEMM_SMEM>>>(adj, buf0, nullptr, buf1, NNODES, NNODES, sAdj, sH, sH);

    // layer 2
    lin<<<gridLin, NTHREADS, GEMM_SMEM>>>(buf1, W2, b2, buf0, 128, 128, 0, 0, 0);
    agg<<<gridAgg, NTHREADS, GEMM_SMEM>>>(adj, buf0, nullptr, buf1, NNODES, NNODES, sAdj, sH, sH);

    // output projection + mask
    final_proj_kernel<<<ROWS_T / 16, 256>>>(buf1, Wout, bout, mask, out);
}

// round 13
// speedup vs baseline: 1.0990x; 1.0990x over previous
#include <cuda_runtime.h>
#include <cstdint>

// =========================================================================
// EuclideanGraphDecoder on GB300 (sm_103a via compute_103 baseline PTX)
// B=8, N=2048, latent=64, hidden=128, out=64, NORM=1.
//
// R13: unified tf32 mma.sync GEMM (CTA 128x128, 8 warps 4Mx2N, warp tile
// 32x64, 3-stage cp.async, one barrier/chunk). Aggregation runs split-K=2
// (256 CTAs -> 2 CTAs/SM) accumulating via atomicAdd into a zeroed buffer;
// ReLU is applied by the consumers (linear A-path / final projection).
// =========================================================================

#define BATCH   8
#define NNODES  2048
#define HID     128
#define ROWS_T  (BATCH * NNODES)     // 16384

__device__ float g_buf0[ROWS_T * HID];     // msg (node-major, tf32-rounded)
__device__ float g_buf1[ROWS_T * HID];     // h pre-relu sums (node-major, fp32)

// ---------------------------------------------------------------- helpers
__device__ __forceinline__ uint32_t cvt_rna_tf32(float x) {
    uint32_t y;
    asm("cvt.rna.tf32.f32 %0, %1;" : "=r"(y) : "f"(x));
    return y;
}
__device__ __forceinline__ uint32_t cvt_rna_tf32_u(uint32_t x) {
    uint32_t y;
    asm("cvt.rna.tf32.f32 %0, %1;" : "=r"(y) : "r"(x));
    return y;
}
__device__ __forceinline__ uint32_t smem_u32(const void* p) {
    uint32_t a;
    asm("{ .reg .u64 t; cvta.to.shared.u64 t, %1; cvt.u32.u64 %0, t; }" : "=r"(a) : "l"(p));
    return a;
}
__device__ __forceinline__ void cp_async16(uint32_t dst, const void* src) {
    asm volatile("cp.async.cg.shared.global [%0], [%1], 16;" :: "r"(dst), "l"(src));
}
#define CP_COMMIT() asm volatile("cp.async.commit_group;" ::: "memory")

__device__ __forceinline__ void ldsm_x4(uint32_t& r0, uint32_t& r1, uint32_t& r2, uint32_t& r3,
                                        uint32_t addr) {
    asm volatile("ldmatrix.sync.aligned.m8n8.x4.shared.b16 {%0,%1,%2,%3}, [%4];"
                 : "=r"(r0), "=r"(r1), "=r"(r2), "=r"(r3) : "r"(addr));
}

__device__ __forceinline__ void mma_tf32(float& c0, float& c1, float& c2, float& c3,
                                         uint32_t a0, uint32_t a1, uint32_t a2, uint32_t a3,
                                         uint32_t b0, uint32_t b1) {
    asm volatile(
        "mma.sync.aligned.m16n8k8.row.col.f32.tf32.tf32.f32 "
        "{%0,%1,%2,%3}, {%4,%5,%6,%7}, {%8,%9}, {%0,%1,%2,%3};"
        : "+f"(c0), "+f"(c1), "+f"(c2), "+f"(c3)
        : "r"(a0), "r"(a1), "r"(a2), "r"(a3), "r"(b0), "r"(b1));
}

// =========================================================================
// Unified tf32 GEMM:
//   C[b, m0:m0+128, 0:128] (+)= op( A[b, m0.., zK:(z+1)K] @ B[b, zK.., 0:128] )
// K here = per-CTA K slice; blockIdx.z selects the slice.
// CTA 128x128, BK=32 chunks, 3-stage cp.async, 8 warps 4(M)x2(N),
// warp tile 32x64 = 2x8 m16n8k8.  2 CTAs/SM.
//   RELUA: relu A elements before tf32 cvt (consumer-side relu)
//   BIAS/ROUND: epilogue bias add / tf32-round output
//   CVTB: round B fragments in registers (raw weights)
//   RED:  accumulate epilogue via atomicAdd (split-K), else plain store
// =========================================================================
#define BK      32
#define STG     3
#define ASTRIDE 36
#define BSTRIDE 136
#define A_FLTS  (128 * ASTRIDE)      // 4608
#define B_FLTS  (BK * BSTRIDE)       // 4352
#define STG_FLTS (A_FLTS + B_FLTS)   // 8960
#define STG_BYTES (STG_FLTS * 4)     // 35840
#define GEMM_SMEM (STG * STG_BYTES)  // 107520 bytes

__device__ __forceinline__ void stage_chunk(uint32_t smb, int s,
                                            const float* Ap, const float* Bp,
                                            int k0, int tid, int lda)
{
    const uint32_t sa = smb + (uint32_t)s * STG_BYTES;
    const uint32_t sb = sa + A_FLTS * 4u;
#pragma unroll
    for (int r = 0; r < 4; r++) {
        const int idx  = tid + 256 * r;
        const int arow = idx >> 3, aseg = idx & 7;
        cp_async16(sa + (uint32_t)(arow * ASTRIDE + aseg * 4) * 4u,
                   Ap + (size_t)arow * lda + k0 + aseg * 4);
        const int brow = idx >> 5, bseg = idx & 31;
        cp_async16(sb + (uint32_t)(brow * BSTRIDE + bseg * 4) * 4u,
                   Bp + (size_t)(k0 + brow) * HID + bseg * 4);
    }
    CP_COMMIT();
}

template<bool RELUA, bool BIAS, bool ROUND, bool CVTB, bool RED>
__global__ __launch_bounds__(256, 2)
void mma_gemm_kernel(const float* __restrict__ A, const float* __restrict__ B,
                     const float* __restrict__ bias, float* __restrict__ C,
                     int K, int lda, size_t sA, size_t sB, size_t sC)
{
    extern __shared__ float smf[];
    const uint32_t smb = smem_u32(smf);

    const int tid   = threadIdx.x;
    const int lane  = tid & 31;
    const int wid   = tid >> 5;
    const int g     = lane >> 2;       // 0..7
    const int tig   = lane & 3;        // 0..3
    const int mbase = (wid & 3) * 32;  // 4 warps along M
    const int nbase = (wid >> 2) * 64; // 2 warps along N

    // ldmatrix per-thread source row/col inside the 16x8 fragment
    const int mi   = lane >> 3;
    const int arow = (lane & 7) + (mi & 1) * 8;
    const int acol = (mi >> 1) * 4;
    uint32_t a_off[2];
#pragma unroll
    for (int t = 0; t < 2; t++)
        a_off[t] = (uint32_t)(((mbase + t * 16 + arow) * ASTRIDE + acol) * 4);

    const int batch = blockIdx.y;
    const int m0    = blockIdx.x * 128;
    const int z     = blockIdx.z;

    const float* Ap = A + (size_t)batch * sA + (size_t)m0 * lda + (size_t)z * K;
    const float* Bp = B + (size_t)batch * sB + (size_t)z * K * HID;

    float acc[2][8][4];
#pragma unroll
    for (int t = 0; t < 2; t++)
#pragma unroll
        for (int u = 0; u < 8; u++)
#pragma unroll
            for (int q = 0; q < 4; q++) acc[t][u][q] = 0.0f;

    const int kiters = K / BK;

    int committed = 0;
#pragma unroll
    for (int p = 0; p < STG - 1; p++)
        if (p < kiters) { stage_chunk(smb, p, Ap, Bp, p * BK, tid, lda); committed++; }

    for (int it = 0; it < kiters; it++) {
        const int pend = committed - it - 1;
        if (pend <= 0)      asm volatile("cp.async.wait_group 0;" ::: "memory");
        else                asm volatile("cp.async.wait_group 1;" ::: "memory");
        __syncthreads();
        // single barrier per chunk: the refill below writes stage (it+2)%3,
        // whose last reads happened at it-1 and are ordered by this barrier.

        if (it + STG - 1 < kiters) {
            stage_chunk(smb, (it + STG - 1) % STG, Ap, Bp, (it + STG - 1) * BK, tid, lda);
            committed++;
        }

        const int st = it % STG;
        const uint32_t sa = smb + (uint32_t)st * STG_BYTES;
        const uint32_t* bsu = (const uint32_t*)(smf + st * STG_FLTS + A_FLTS);

#pragma unroll
        for (int ks = 0; ks < 4; ks++) {
            const int k = ks * 8;
            uint32_t af[2][4];
#pragma unroll
            for (int t = 0; t < 2; t++) {
                ldsm_x4(af[t][0], af[t][1], af[t][2], af[t][3],
                        sa + a_off[t] + (uint32_t)(k * 4));
#pragma unroll
                for (int q = 0; q < 4; q++) {
                    if (RELUA) {
                        float f = fmaxf(__uint_as_float(af[t][q]), 0.0f);
                        af[t][q] = cvt_rna_tf32(f);
                    } else {
                        af[t][q] = cvt_rna_tf32_u(af[t][q]);
                    }
                }
            }
#pragma unroll
            for (int u = 0; u < 8; u++) {
                const int n = nbase + u * 8 + g;
                uint32_t b0 = bsu[(k + tig) * BSTRIDE + n];
                uint32_t b1 = bsu[(k + tig + 4) * BSTRIDE + n];
                if (CVTB) { b0 = cvt_rna_tf32_u(b0); b1 = cvt_rna_tf32_u(b1); }
#pragma unroll
                for (int t = 0; t < 2; t++)
                    mma_tf32(acc[t][u][0], acc[t][u][1], acc[t][u][2], acc[t][u][3],
                             af[t][0], af[t][1], af[t][2], af[t][3], b0, b1);
            }
        }
    }

    // ---- epilogue ----
    float* Cp = C + (size_t)batch * sC + (size_t)m0 * HID;
#pragma unroll
    for (int t = 0; t < 2; t++) {
        const int r0 = mbase + t * 16 + g;
#pragma unroll
        for (int u = 0; u < 8; u++) {
            const int c = nbase + u * 8 + 2 * tig;
            float v[4] = { acc[t][u][0], acc[t][u][1], acc[t][u][2], acc[t][u][3] };
            if (BIAS) {
                const float bc0 = bias[c], bc1 = bias[c + 1];
                v[0] += bc0; v[1] += bc1; v[2] += bc0; v[3] += bc1;
            }
#pragma unroll
            for (int q = 0; q < 4; q++)
                if (ROUND) v[q] = __uint_as_float(cvt_rna_tf32(v[q]));
            if (RED) {
                atomicAdd(Cp + (size_t)r0 * HID + c,           v[0]);
                atomicAdd(Cp + (size_t)r0 * HID + c + 1,       v[1]);
                atomicAdd(Cp + (size_t)(r0 + 8) * HID + c,     v[2]);
                atomicAdd(Cp + (size_t)(r0 + 8) * HID + c + 1, v[3]);
            } else {
                float2 v0 = { v[0], v[1] };
                float2 v1 = { v[2], v[3] };
                *(float2*)(Cp + (size_t)r0 * HID + c)       = v0;
                *(float2*)(Cp + (size_t)(r0 + 8) * HID + c) = v1;
            }
        }
    }
}

// =========================================================================
// Zero a float buffer (for split-K accumulation)
// =========================================================================
__global__ __launch_bounds__(256)
void zero_kernel(float* __restrict__ p)
{
    const size_t n4 = (size_t)ROWS_T * HID / 4;
    const size_t stride = (size_t)gridDim.x * 256;
    const float4 z = {0.f, 0.f, 0.f, 0.f};
    for (size_t i = (size_t)blockIdx.x * 256 + threadIdx.x; i < n4; i += stride)
        ((float4*)p)[i] = z;
}

// =========================================================================
// Output projection: out = (relu(h) @ Wout + bout) * mask   (fp32 FFMA)
// =========================================================================
__global__ __launch_bounds__(256)
void final_proj_kernel(const float* __restrict__ h, const float* __restrict__ W,
                       const float* __restrict__ bias, const float* __restrict__ mask,
                       float* __restrict__ out)
{
    __shared__ float Ws[128][64];
    __shared__ float xs[16][128];
    __shared__ float bs[64];

    const int tid = threadIdx.x;
    for (int i = tid; i < 2048; i += 256)
        ((float4*)&Ws[0][0])[i] = ((const float4*)W)[i];
    if (tid < 64) bs[tid] = bias[tid];

    const int row0 = blockIdx.x * 16;
    for (int i = tid; i < 512; i += 256)
        ((float4*)&xs[0][0])[i] = *(const float4*)(h + (size_t)row0 * 128 + i * 4);
    __syncthreads();

    const int rl = tid >> 4;
    const int c4 = (tid & 15) * 4;

    float acc[4];
#pragma unroll
    for (int q = 0; q < 4; q++) acc[q] = bs[c4 + q];

#pragma unroll 8
    for (int d = 0; d < 128; d++) {
        const float x = fmaxf(xs[rl][d], 0.0f);     // deferred relu
        const float4 w = *(const float4*)&Ws[d][c4];
        acc[0] += x * w.x;
        acc[1] += x * w.y;
        acc[2] += x * w.z;
        acc[3] += x * w.w;
    }

    const float m = mask[row0 + rl];
    float4 v = {acc[0] * m, acc[1] * m, acc[2] * m, acc[3] * m};
    *(float4*)(out + (size_t)(row0 + rl) * 64 + c4) = v;
}

// =========================================================================
// Launcher
// =========================================================================
extern "C" void kernel_launch(void* const* d_in, const int* in_sizes, int n_in,
                              void* d_out, int out_size)
{
    const float* latent = (const float*)d_in[0];
    const float* adj    = (const float*)d_in[1];
    const float* mask   = (const float*)d_in[2];
    const float* W0     = (const float*)d_in[3];
    const float* b0     = (const float*)d_in[4];
    const float* W1     = (const float*)d_in[5];
    const float* b1     = (const float*)d_in[6];
    const float* W2     = (const float*)d_in[7];
    const float* b2     = (const float*)d_in[8];
    const float* Wout   = (const float*)d_in[9];
    const float* bout   = (const float*)d_in[10];
    float*       out    = (float*)d_out;

    float *buf0 = nullptr, *buf1 = nullptr;
    cudaGetSymbolAddress((void**)&buf0, g_buf0);
    cudaGetSymbolAddress((void**)&buf1, g_buf1);

    // lin0: no relu on A (latent), bias+round, cvt weights, store
    auto lin0 = mma_gemm_kernel<false, true, true, true, false>;
    // lin1/2: relu on A (raw agg sums), bias+round, cvt weights, store
    auto linR = mma_gemm_kernel<true, true, true, true, false>;
    // agg: raw adj A (cvt only), B pre-rounded, atomic-accumulate, no relu
    auto agg  = mma_gemm_kernel<false, false, false, false, true>;
    cudaFuncSetAttribute(lin0, cudaFuncAttributeMaxDynamicSharedMemorySize, GEMM_SMEM);
    cudaFuncSetAttribute(linR, cudaFuncAttributeMaxDynamicSharedMemorySize, GEMM_SMEM);
    cudaFuncSetAttribute(agg,  cudaFuncAttributeMaxDynamicSharedMemorySize, GEMM_SMEM);

    const dim3 gridLin(ROWS_T / 128, 1, 1);        // 128 CTAs
    const dim3 gridAgg(NNODES / 128, BATCH, 2);    // 16 x 8 x 2 = 256 CTAs (split-K)
    const int  KSUB = NNODES / 2;                  // 1024 per split
    const size_t sAdj = (size_t)NNODES * NNODES;
    const size_t sH   = (size_t)NNODES * HID;

    // layer 0
    lin0<<<gridLin, 256, GEMM_SMEM>>>(latent, W0, b0, buf0, 64, 64, 0, 0, 0);
    zero_kernel<<<256, 256>>>(buf1);
    agg<<<gridAgg, 256, GEMM_SMEM>>>(adj, buf0, nullptr, buf1, KSUB, NNODES, sAdj, sH, sH);

    // layer 1
    linR<<<gridLin, 256, GEMM_SMEM>>>(buf1, W1, b1, buf0, 128, 128, 0, 0, 0);
    zero_kernel<<<256, 256>>>(buf1);
    agg<<<gridAgg, 256, GEMM_SMEM>>>(adj, buf0, nullptr, buf1, KSUB, NNODES, sAdj, sH, sH);

    // layer 2
    linR<<<gridLin, 256, GEMM_SMEM>>>(buf1, W2, b2, buf0, 128, 128, 0, 0, 0);
    zero_kernel<<<256, 256>>>(buf1);
    agg<<<gridAgg, 256, GEMM_SMEM>>>(adj, buf0, nullptr, buf1, KSUB, NNODES, sAdj, sH, sH);

    // output projection + mask (relu applied on read)
    final_proj_kernel<<<ROWS_T / 16, 256>>>(buf1, Wout, bout, mask, out);
}

// round 15
// speedup vs baseline: 1.3606x; 1.2380x over previous
#include <cuda_runtime.h>
#include <cuda_fp16.h>
#include <cstdint>

// =========================================================================
// EuclideanGraphDecoder on GB300 (sm_103a via compute_103 baseline PTX)
// B=8, N=2048, latent=64, hidden=128, out=64, NORM=1.
//
// R14: aggregation GEMM moved to fp16 m16n8k16 (same 10-bit mantissa as
// tf32, half the MMA instructions). fp16 adjacency converted once; msg
// transposed+fp16 per layer; split-K=2 into two partial buffers (no
// atomics); linears are single-stage tf32 mma kernels; consumers apply
// relu(p0+p1).
// =========================================================================

#define BATCH   8
#define NNODES  2048
#define HID     128
#define ROWS_T  (BATCH * NNODES)     // 16384

__device__ float  g_buf0[ROWS_T * HID];            // msg (node-major fp32)
__device__ float  g_p0[ROWS_T * HID];              // agg partial z=0
__device__ float  g_p1[ROWS_T * HID];              // agg partial z=1
__device__ __half g_msgT16[(size_t)BATCH * HID * NNODES];        // msg^T fp16
__device__ __half g_adj16[(size_t)BATCH * NNODES * NNODES];      // adj fp16

// ---------------------------------------------------------------- helpers
__device__ __forceinline__ uint32_t cvt_rna_tf32_u(uint32_t x) {
    uint32_t y;
    asm("cvt.rna.tf32.f32 %0, %1;" : "=r"(y) : "r"(x));
    return y;
}
__device__ __forceinline__ uint32_t smem_u32(const void* p) {
    uint32_t a;
    asm("{ .reg .u64 t; cvta.to.shared.u64 t, %1; cvt.u32.u64 %0, t; }" : "=r"(a) : "l"(p));
    return a;
}
__device__ __forceinline__ void cp_async16(uint32_t dst, const void* src) {
    asm volatile("cp.async.cg.shared.global [%0], [%1], 16;" :: "r"(dst), "l"(src));
}
#define CP_COMMIT() asm volatile("cp.async.commit_group;" ::: "memory")

__device__ __forceinline__ void ldsm_x4(uint32_t& r0, uint32_t& r1, uint32_t& r2, uint32_t& r3,
                                        uint32_t addr) {
    asm volatile("ldmatrix.sync.aligned.m8n8.x4.shared.b16 {%0,%1,%2,%3}, [%4];"
                 : "=r"(r0), "=r"(r1), "=r"(r2), "=r"(r3) : "r"(addr));
}

__device__ __forceinline__ void mma_tf32(float& c0, float& c1, float& c2, float& c3,
                                         uint32_t a0, uint32_t a1, uint32_t a2, uint32_t a3,
                                         uint32_t b0, uint32_t b1) {
    asm volatile(
        "mma.sync.aligned.m16n8k8.row.col.f32.tf32.tf32.f32 "
        "{%0,%1,%2,%3}, {%4,%5,%6,%7}, {%8,%9}, {%0,%1,%2,%3};"
        : "+f"(c0), "+f"(c1), "+f"(c2), "+f"(c3)
        : "r"(a0), "r"(a1), "r"(a2), "r"(a3), "r"(b0), "r"(b1));
}
__device__ __forceinline__ void mma_f16(float& c0, float& c1, float& c2, float& c3,
                                        uint32_t a0, uint32_t a1, uint32_t a2, uint32_t a3,
                                        uint32_t b0, uint32_t b1) {
    asm volatile(
        "mma.sync.aligned.m16n8k16.row.col.f32.f16.f16.f32 "
        "{%0,%1,%2,%3}, {%4,%5,%6,%7}, {%8,%9}, {%0,%1,%2,%3};"
        : "+f"(c0), "+f"(c1), "+f"(c2), "+f"(c3)
        : "r"(a0), "r"(a1), "r"(a2), "r"(a3), "r"(b0), "r"(b1));
}

// =========================================================================
// adj fp32 -> fp16 (once per launch)
// =========================================================================
__global__ __launch_bounds__(256)
void adjcvt_kernel(const float* __restrict__ in, __half* __restrict__ out)
{
    const size_t n4 = (size_t)BATCH * NNODES * NNODES / 4;
    const size_t stride = (size_t)gridDim.x * 256;
    for (size_t i = (size_t)blockIdx.x * 256 + threadIdx.x; i < n4; i += stride) {
        float4 v = ((const float4*)in)[i];
        __half2 h0 = __floats2half2_rn(v.x, v.y);
        __half2 h1 = __floats2half2_rn(v.z, v.w);
        uint2 u = { *(uint32_t*)&h0, *(uint32_t*)&h1 };
        ((uint2*)out)[i] = u;
    }
}

// =========================================================================
// msg fp32 [b*2048][128] -> msgT16 fp16 [b][128][2048]
// tile: 64 nodes x 32 feats
// =========================================================================
__global__ __launch_bounds__(256)
void cvtT_kernel(const float* __restrict__ msg, __half* __restrict__ msgT)
{
    __shared__ __half st[32][72];   // [feat][node], pad 8
    const int b  = blockIdx.z;
    const int n0 = blockIdx.x * 64;
    const int f0 = blockIdx.y * 32;
    const int tid = threadIdx.x;

#pragma unroll
    for (int r = 0; r < 2; r++) {
        const int idx = tid + 256 * r;          // 0..511
        const int row = idx >> 3;               // node local 0..63
        const int c4  = idx & 7;                // float4 within 32 feats
        float4 v = *(const float4*)(msg + ((size_t)(b * NNODES + n0 + row)) * HID + f0 + c4 * 4);
        st[c4 * 4 + 0][row] = __float2half_rn(v.x);
        st[c4 * 4 + 1][row] = __float2half_rn(v.y);
        st[c4 * 4 + 2][row] = __float2half_rn(v.z);
        st[c4 * 4 + 3][row] = __float2half_rn(v.w);
    }
    __syncthreads();

#pragma unroll
    for (int r = 0; r < 2; r++) {
        const int idx = tid + 256 * r;          // 0..511 -> need 32x32=1024 u32? no: 32 rows x 32 u32 = 1024
        const int fr = idx >> 5;                // 0..15 (+16 with r loop up to 511 -> fr 0..15) 
        const int nc = idx & 31;
        // two r-iterations cover fr 0..15; need 32 rows -> do 2 more below
        uint32_t w = *(uint32_t*)&st[fr][2 * nc];
        *(uint32_t*)(msgT + ((size_t)(b * HID + f0 + fr)) * NNODES + n0 + 2 * nc) = w;
        uint32_t w2 = *(uint32_t*)&st[fr + 16][2 * nc];
        *(uint32_t*)(msgT + ((size_t)(b * HID + f0 + fr + 16)) * NNODES + n0 + 2 * nc) = w2;
    }
}

// =========================================================================
// Aggregation GEMM (fp16 m16n8k16, split-K=2):
//   p{z}[b, m0:m0+128, 0:128] = adj16[b, m0.., zK..] @ msgT16[b, :, zK..]^T
// CTA 128x128, BK=32 (2 k16 steps), 4-stage cp.async, 8 warps 4Mx2N,
// warp tile 32x64.  2 CTAs/SM.
// =========================================================================
#define BKA      32
#define AST_H    40                       // A smem row stride in halves (80B)
#define BST_H    40                       // B^T smem row stride in halves
#define A_BYTES  (128 * AST_H * 2)        // 10240
#define B_BYTES  (128 * BST_H * 2)        // 10240
#define STG      4
#define STG_B    (A_BYTES + B_BYTES)      // 20480
#define AGG_SMEM (STG * STG_B)            // 81920

__device__ __forceinline__ void agg_stage(uint32_t smb, int s,
                                          const __half* Ap, const __half* Bp, int k0, int tid)
{
    const uint32_t sa = smb + (uint32_t)s * STG_B;
    const uint32_t sb = sa + A_BYTES;
    // A: 128 rows x 32 halves (64B) = 512 x16B ; B: 128 feat rows x 32 halves = 512 x16B
#pragma unroll
    for (int r = 0; r < 2; r++) {
        const int idx = tid + 256 * r;
        const int row = idx >> 2, seg = idx & 3;
        cp_async16(sa + (uint32_t)(row * AST_H * 2 + seg * 16),
                   Ap + (size_t)row * NNODES + k0 + seg * 8);
        cp_async16(sb + (uint32_t)(row * BST_H * 2 + seg * 16),
                   Bp + (size_t)row * NNODES + k0 + seg * 8);
    }
    CP_COMMIT();
}

__global__ __launch_bounds__(256, 2)
void agg_f16_kernel(const __half* __restrict__ adj16, const __half* __restrict__ msgT16,
                    float* __restrict__ P0, float* __restrict__ P1)
{
    extern __shared__ char smc[];
    const uint32_t smb = smem_u32(smc);

    const int tid   = threadIdx.x;
    const int lane  = tid & 31;
    const int wid   = tid >> 5;
    const int g     = lane >> 2;
    const int tig   = lane & 3;
    const int mbase = (wid & 3) * 32;   // 4 warps along M
    const int nbase = (wid >> 2) * 64;  // 2 warps along N

    // ldmatrix source mapping (b16): matrices (m0,m1,m2,m3) = (r0-7,c0)(r8-15,c0)(r0-7,c8)(r8-15,c8)
    const int mi   = lane >> 3;
    const int arow = (lane & 7) + (mi & 1) * 8;
    const int acol = (mi >> 1) * 8;     // halves
    uint32_t a_off[2];
#pragma unroll
    for (int t = 0; t < 2; t++)
        a_off[t] = (uint32_t)(((mbase + t * 16 + arow) * AST_H + acol) * 2);

    const int batch = blockIdx.y;
    const int m0    = blockIdx.x * 128;
    const int z     = blockIdx.z;
    const int KSUB  = NNODES / 2;       // 1024

    const __half* Ap = adj16  + (size_t)batch * NNODES * NNODES + (size_t)m0 * NNODES + (size_t)z * KSUB;
    const __half* Bp = msgT16 + (size_t)batch * HID * NNODES + (size_t)z * KSUB;
    float* Cp = (z == 0 ? P0 : P1) + (size_t)batch * NNODES * HID + (size_t)m0 * HID;

    float acc[2][8][4];
#pragma unroll
    for (int t = 0; t < 2; t++)
#pragma unroll
        for (int u = 0; u < 8; u++)
#pragma unroll
            for (int q = 0; q < 4; q++) acc[t][u][q] = 0.0f;

    const int kiters = KSUB / BKA;      // 32

    int committed = 0;
#pragma unroll
    for (int p = 0; p < STG - 1; p++) { agg_stage(smb, p, Ap, Bp, p * BKA, tid); committed++; }

    for (int it = 0; it < kiters; it++) {
        const int pend = committed - it - 1;
        if (pend <= 0)      asm volatile("cp.async.wait_group 0;" ::: "memory");
        else if (pend == 1) asm volatile("cp.async.wait_group 1;" ::: "memory");
        else                asm volatile("cp.async.wait_group 2;" ::: "memory");
        __syncthreads();

        if (it + STG - 1 < kiters) {
            agg_stage(smb, (it + STG - 1) & (STG - 1), Ap, Bp, (it + STG - 1) * BKA, tid);
            committed++;
        }

        const int st = it & (STG - 1);
        const uint32_t sa = smb + (uint32_t)st * STG_B;
        const uint32_t* bsu = (const uint32_t*)(smc + st * STG_B + A_BYTES);

#pragma unroll
        for (int ks = 0; ks < 2; ks++) {       // two k16 steps per 32-chunk
            uint32_t af[2][4];
#pragma unroll
            for (int t = 0; t < 2; t++)
                ldsm_x4(af[t][0], af[t][1], af[t][2], af[t][3],
                        sa + a_off[t] + (uint32_t)(ks * 32));    // 16 halves = 32B
#pragma unroll
            for (int u = 0; u < 8; u++) {
                const int n = nbase + u * 8 + g;
                const uint32_t b0 = bsu[n * (BST_H / 2) + ks * 8 + tig];
                const uint32_t b1 = bsu[n * (BST_H / 2) + ks * 8 + tig + 4];
#pragma unroll
                for (int t = 0; t < 2; t++)
                    mma_f16(acc[t][u][0], acc[t][u][1], acc[t][u][2], acc[t][u][3],
                            af[t][0], af[t][1], af[t][2], af[t][3], b0, b1);
            }
        }
    }

    // epilogue: plain store partials (no relu here)
#pragma unroll
    for (int t = 0; t < 2; t++) {
        const int r0 = mbase + t * 16 + g;
#pragma unroll
        for (int u = 0; u < 8; u++) {
            const int c = nbase + u * 8 + 2 * tig;
            float2 v0 = { acc[t][u][0], acc[t][u][1] };
            float2 v1 = { acc[t][u][2], acc[t][u][3] };
            *(float2*)(Cp + (size_t)r0 * HID + c)       = v0;
            *(float2*)(Cp + (size_t)(r0 + 8) * HID + c) = v1;
        }
    }
}

// =========================================================================
// Linear layer (tf32, single-stage, K fully smem-resident, K in {64,128}):
//   C[m0:m0+128, :] = op(A) @ W + b,  op(A) = SUMA ? relu(A0+A1) : A0
// 8 warps 4Mx2N, warp tile 32x64.
// =========================================================================
template<int KT, bool SUMA>
__global__ __launch_bounds__(256, 1)
void lin_kernel(const float* __restrict__ A0, const float* __restrict__ A1,
                const float* __restrict__ W, const float* __restrict__ bias,
                float* __restrict__ C)
{
    constexpr int AST = KT + 4;
    constexpr int BST = 136;
    extern __shared__ float smf[];
    float* As = smf;                       // [128][AST]
    float* Bs = smf + 128 * AST;           // [KT][BST]
    const uint32_t smb = smem_u32(smf);

    const int tid   = threadIdx.x;
    const int lane  = tid & 31;
    const int wid   = tid >> 5;
    const int g     = lane >> 2;
    const int tig   = lane & 3;
    const int mbase = (wid & 3) * 32;
    const int nbase = (wid >> 2) * 64;

    const int mi   = lane >> 3;
    const int arow = (lane & 7) + (mi & 1) * 8;
    const int acol = (mi >> 1) * 4;        // floats
    uint32_t a_off[2];
#pragma unroll
    for (int t = 0; t < 2; t++)
        a_off[t] = (uint32_t)(((mbase + t * 16 + arow) * AST + acol) * 4);

    const int m0 = blockIdx.x * 128;

    // stage A (full K)
#pragma unroll
    for (int r = 0; r < (128 * KT / 4) / 256; r++) {
        const int idx  = tid + 256 * r;
        const int row  = idx / (KT / 4);
        const int c4   = idx % (KT / 4);
        float4 v = *(const float4*)(A0 + (size_t)(m0 + row) * KT + c4 * 4);
        if (SUMA) {
            float4 w = *(const float4*)(A1 + (size_t)(m0 + row) * KT + c4 * 4);
            v.x = fmaxf(v.x + w.x, 0.f); v.y = fmaxf(v.y + w.y, 0.f);
            v.z = fmaxf(v.z + w.z, 0.f); v.w = fmaxf(v.w + w.w, 0.f);
        }
        *(float4*)(As + row * AST + c4 * 4) = v;
    }
    // stage W (full K)
#pragma unroll
    for (int r = 0; r < (KT * 128 / 4) / 256; r++) {
        const int idx  = tid + 256 * r;
        const int row  = idx >> 5;
        const int c4   = idx & 31;
        float4 v = *(const float4*)(W + (size_t)row * HID + c4 * 4);
        *(float4*)(Bs + row * BST + c4 * 4) = v;
    }
    __syncthreads();

    float acc[2][8][4];
#pragma unroll
    for (int t = 0; t < 2; t++)
#pragma unroll
        for (int u = 0; u < 8; u++)
#pragma unroll
            for (int q = 0; q < 4; q++) acc[t][u][q] = 0.0f;

    const uint32_t* bsu = (const uint32_t*)Bs;

#pragma unroll
    for (int ks = 0; ks < KT / 8; ks++) {
        const int k = ks * 8;
        uint32_t af[2][4];
#pragma unroll
        for (int t = 0; t < 2; t++) {
            ldsm_x4(af[t][0], af[t][1], af[t][2], af[t][3],
                    smb + a_off[t] + (uint32_t)(k * 4));
#pragma unroll
            for (int q = 0; q < 4; q++) af[t][q] = cvt_rna_tf32_u(af[t][q]);
        }
#pragma unroll
        for (int u = 0; u < 8; u++) {
            const int n = nbase + u * 8 + g;
            uint32_t b0 = cvt_rna_tf32_u(bsu[(k + tig) * BST + n]);
            uint32_t b1 = cvt_rna_tf32_u(bsu[(k + tig + 4) * BST + n]);
#pragma unroll
            for (int t = 0; t < 2; t++)
                mma_tf32(acc[t][u][0], acc[t][u][1], acc[t][u][2], acc[t][u][3],
                         af[t][0], af[t][1], af[t][2], af[t][3], b0, b1);
        }
    }

    float* Cp = C + (size_t)m0 * HID;
#pragma unroll
    for (int t = 0; t < 2; t++) {
        const int r0 = mbase + t * 16 + g;
#pragma unroll
        for (int u = 0; u < 8; u++) {
            const int c = nbase + u * 8 + 2 * tig;
            const float bc0 = bias[c], bc1 = bias[c + 1];
            float2 v0 = { acc[t][u][0] + bc0, acc[t][u][1] + bc1 };
            float2 v1 = { acc[t][u][2] + bc0, acc[t][u][3] + bc1 };
            *(float2*)(Cp + (size_t)r0 * HID + c)       = v0;
            *(float2*)(Cp + (size_t)(r0 + 8) * HID + c) = v1;
        }
    }
}

// =========================================================================
// Output projection: out = (relu(p0+p1) @ Wout + bout) * mask
// =========================================================================
__global__ __launch_bounds__(256)
void final_proj_kernel(const float* __restrict__ h0, const float* __restrict__ h1,
                       const float* __restrict__ W, const float* __restrict__ bias,
                       const float* __restrict__ mask, float* __restrict__ out)
{
    __shared__ float Ws[128][64];
    __shared__ float xs[16][128];
    __shared__ float bs[64];

    const int tid = threadIdx.x;
    for (int i = tid; i < 2048; i += 256)
        ((float4*)&Ws[0][0])[i] = ((const float4*)W)[i];
    if (tid < 64) bs[tid] = bias[tid];

    const int row0 = blockIdx.x * 16;
    for (int i = tid; i < 512; i += 256) {
        float4 a = *(const float4*)(h0 + (size_t)row0 * 128 + i * 4);
        float4 b = *(const float4*)(h1 + (size_t)row0 * 128 + i * 4);
        float4 v = { fmaxf(a.x + b.x, 0.f), fmaxf(a.y + b.y, 0.f),
                     fmaxf(a.z + b.z, 0.f), fmaxf(a.w + b.w, 0.f) };
        ((float4*)&xs[0][0])[i] = v;
    }
    __syncthreads();

    const int rl = tid >> 4;
    const int c4 = (tid & 15) * 4;

    float acc[4];
#pragma unroll
    for (int q = 0; q < 4; q++) acc[q] = bs[c4 + q];

#pragma unroll 8
    for (int d = 0; d < 128; d++) {
        const float x = xs[rl][d];
        const float4 w = *(const float4*)&Ws[d][c4];
        acc[0] += x * w.x;
        acc[1] += x * w.y;
        acc[2] += x * w.z;
        acc[3] += x * w.w;
    }

    const float m = mask[row0 + rl];
    float4 v = {acc[0] * m, acc[1] * m, acc[2] * m, acc[3] * m};
    *(float4*)(out + (size_t)(row0 + rl) * 64 + c4) = v;
}

// =========================================================================
// Launcher
// =========================================================================
extern "C" void kernel_launch(void* const* d_in, const int* in_sizes, int n_in,
                              void* d_out, int out_size)
{
    const float* latent = (const float*)d_in[0];
    const float* adj    = (const float*)d_in[1];
    const float* mask   = (const float*)d_in[2];
    const float* W0     = (const float*)d_in[3];
    const float* b0     = (const float*)d_in[4];
    const float* W1     = (const float*)d_in[5];
    const float* b1     = (const float*)d_in[6];
    const float* W2     = (const float*)d_in[7];
    const float* b2     = (const float*)d_in[8];
    const float* Wout   = (const float*)d_in[9];
    const float* bout   = (const float*)d_in[10];
    float*       out    = (float*)d_out;

    float  *buf0, *p0, *p1;
    __half *msgT16, *adj16;
    cudaGetSymbolAddress((void**)&buf0,   g_buf0);
    cudaGetSymbolAddress((void**)&p0,     g_p0);
    cudaGetSymbolAddress((void**)&p1,     g_p1);
    cudaGetSymbolAddress((void**)&msgT16, g_msgT16);
    cudaGetSymbolAddress((void**)&adj16,  g_adj16);

    auto lin0 = lin_kernel<64, false>;
    auto linR = lin_kernel<128, true>;
    const int LIN0_SMEM = (128 * 68 + 64 * 136) * 4;     // 69632
    const int LINR_SMEM = (128 * 132 + 128 * 136) * 4;   // 137216
    cudaFuncSetAttribute(lin0, cudaFuncAttributeMaxDynamicSharedMemorySize, LIN0_SMEM);
    cudaFuncSetAttribute(linR, cudaFuncAttributeMaxDynamicSharedMemorySize, LINR_SMEM);
    cudaFuncSetAttribute(agg_f16_kernel, cudaFuncAttributeMaxDynamicSharedMemorySize, AGG_SMEM);

    const dim3 gridLin(ROWS_T / 128);
    const dim3 gridAgg(NNODES / 128, BATCH, 2);              // 256 CTAs
    const dim3 gridCvtT(NNODES / 64, HID / 32, BATCH);

    // one-time: fp16 adjacency
    adjcvt_kernel<<<2048, 256>>>(adj, adj16);

    // layer 0
    lin0<<<gridLin, 256, LIN0_SMEM>>>(latent, nullptr, W0, b0, buf0);
    cvtT_kernel<<<gridCvtT, 256>>>(buf0, msgT16);
    agg_f16_kernel<<<gridAgg, 256, AGG_SMEM>>>(adj16, msgT16, p0, p1);

    // layer 1
    linR<<<gridLin, 256, LINR_SMEM>>>(p0, p1, W1, b1, buf0);
    cvtT_kernel<<<gridCvtT, 256>>>(buf0, msgT16);
    agg_f16_kernel<<<gridAgg, 256, AGG_SMEM>>>(adj16, msgT16, p0, p1);

    // layer 2
    linR<<<gridLin, 256, LINR_SMEM>>>(p0, p1, W2, b2, buf0);
    cvtT_kernel<<<gridCvtT, 256>>>(buf0, msgT16);
    agg_f16_kernel<<<gridAgg, 256, AGG_SMEM>>>(adj16, msgT16, p0, p1);

    // output projection + mask
    final_proj_kernel<<<ROWS_T / 16, 256>>>(p0, p1, Wout, bout, mask, out);
}